// round 3
// baseline (speedup 1.0000x reference)
#include <cuda_runtime.h>
#include <math.h>

#define MAX_N 100000
#define MAX_E 600000

// Split node records for gather density:
__device__ float g_QU [(size_t)MAX_N * 384];   // q(128) | u0(128) | u1(128)  (dst side)
__device__ float g_KV [(size_t)MAX_N * 256];   // k(128) | v(128)             (src side)
__device__ float g_acc[(size_t)MAX_N * 384];   // v_norm(128) | e0_norm(128) | e1_norm(128)
__device__ float g_Bcat[128 * 768];
__device__ float g_bcat[768];
__device__ float g_Bblk[256 * 128];
// Edge binning
__device__ int  g_cnt[MAX_N];
__device__ int  g_off[MAX_N];
__device__ int  g_cur[MAX_N];
__device__ int  g_bsum[256];
__device__ int2 g_edges[MAX_E];                // (src, e) grouped by dst

// ---------------------------------------------------------------------------
// SGEMM: 128 threads, BM=128, BN=128, BK=16, 16x8 microtile, cp.async dbuf.
// mode==0: plain C (ldc) with optional accum. mode==1: split projection write
// (cols 0..383 -> g_QU, 384..639 -> g_KV, 640..767 -> C as out[N,128]).
// ---------------------------------------------------------------------------
__device__ __forceinline__ void cp16(unsigned dst, const void* src) {
    asm volatile("cp.async.cg.shared.global [%0], [%1], 16;" :: "r"(dst), "l"(src));
}

__global__ __launch_bounds__(128) void sgemm_v2(
    const float* __restrict__ A, int lda,
    const float* __restrict__ B, int ldb,
    float* __restrict__ C, int ldc,
    int M, int K,
    const float* __restrict__ bias, int accum, int mode)
{
    __shared__ float As[2][16][132];
    __shared__ float Bs[2][16][128];
    const int tid = threadIdx.x;
    const int tx = tid & 15, ty = tid >> 4;
    const int bm0 = blockIdx.x * 128;
    const int bn0 = blockIdx.y * 128;

    float acc[16][8];
#pragma unroll
    for (int i = 0; i < 16; i++)
#pragma unroll
        for (int j = 0; j < 8; j++) acc[i][j] = 0.f;

    float4 areg[4];
    const int ntiles = K >> 4;

    auto ldgA = [&](int kt) {
#pragma unroll
        for (int i = 0; i < 4; i++) {
            int fidx = tid + 128 * i;
            int row = bm0 + (fidx >> 2);
            int c = kt * 16 + (fidx & 3) * 4;
            areg[i] = (row < M) ? *(const float4*)&A[(size_t)row * lda + c]
                                : make_float4(0.f, 0.f, 0.f, 0.f);
        }
    };
    auto stsA = [&](int buf) {
#pragma unroll
        for (int i = 0; i < 4; i++) {
            int fidx = tid + 128 * i;
            int row = fidx >> 2;
            int c = (fidx & 3) * 4;
            As[buf][c + 0][row] = areg[i].x;
            As[buf][c + 1][row] = areg[i].y;
            As[buf][c + 2][row] = areg[i].z;
            As[buf][c + 3][row] = areg[i].w;
        }
    };
    auto cpB = [&](int kt, int buf) {
#pragma unroll
        for (int i = 0; i < 4; i++) {
            int idx = tid + 128 * i;
            int row = idx >> 5;
            int c4 = (idx & 31) * 4;
            unsigned dst = (unsigned)__cvta_generic_to_shared(&Bs[buf][row][c4]);
            cp16(dst, &B[(size_t)(kt * 16 + row) * ldb + bn0 + c4]);
        }
        asm volatile("cp.async.commit_group;");
    };

    ldgA(0);
    stsA(0);
    cpB(0, 0);
    asm volatile("cp.async.wait_group 0;");
    __syncthreads();

    for (int t = 0; t < ntiles; t++) {
        int cur = t & 1, nxt = cur ^ 1;
        bool more = (t + 1 < ntiles);
        if (more) {
            ldgA(t + 1);
            cpB(t + 1, nxt);
        }
#pragma unroll
        for (int kk = 0; kk < 16; kk++) {
            float a[16], b[8];
            *(float4*)&a[0]  = *(const float4*)&As[cur][kk][ty * 16 + 0];
            *(float4*)&a[4]  = *(const float4*)&As[cur][kk][ty * 16 + 4];
            *(float4*)&a[8]  = *(const float4*)&As[cur][kk][ty * 16 + 8];
            *(float4*)&a[12] = *(const float4*)&As[cur][kk][ty * 16 + 12];
#pragma unroll
            for (int j = 0; j < 8; j++) b[j] = Bs[cur][kk][tx + 16 * j];
#pragma unroll
            for (int i = 0; i < 16; i++)
#pragma unroll
                for (int j = 0; j < 8; j++)
                    acc[i][j] = fmaf(a[i], b[j], acc[i][j]);
        }
        if (more) {
            stsA(nxt);
            asm volatile("cp.async.wait_group 0;");
        }
        __syncthreads();
    }

#pragma unroll
    for (int i = 0; i < 16; i++) {
        int row = bm0 + ty * 16 + i;
        if (row >= M) break;
#pragma unroll
        for (int j = 0; j < 8; j++) {
            int col = bn0 + tx + 16 * j;
            float v = acc[i][j];
            if (bias) v += bias[col];
            float* cp;
            if (mode == 0) {
                cp = &C[(size_t)row * ldc + col];
            } else {
                if (bn0 < 384)      cp = &g_QU[(size_t)row * 384 + col];
                else if (bn0 < 640) cp = &g_KV[(size_t)row * 256 + (col - 384)];
                else                cp = &C[(size_t)row * 128 + (col - 640)];
            }
            if (accum) v += *cp;
            *cp = v;
        }
    }
}

// ---------------------------------------------------------------------------
// Prep kernels
// ---------------------------------------------------------------------------
__global__ __launch_bounds__(128) void prep_bcat(
    const float* __restrict__ Wq, const float* __restrict__ bq,
    const float* __restrict__ Wk, const float* __restrict__ bk,
    const float* __restrict__ Wv, const float* __restrict__ bv,
    const float* __restrict__ Ws, const float* __restrict__ bs,
    const float* __restrict__ We)
{
    int j = blockIdx.x;      // 0..767
    int r = threadIdx.x;     // 0..127
    float v;
    if (j < 128) v = Wq[r * 128 + j];
    else if (j < 256) {
        int d = j - 128; const float* w = We + d * 128;
        float s = 0.f;
#pragma unroll
        for (int c = 0; c < 64; c++) s = fmaf(Wq[r * 128 + c], w[c], s);
        v = s;
    } else if (j < 384) {
        int d = j - 256; const float* w = We + d * 128 + 64;
        float s = 0.f;
#pragma unroll
        for (int c = 0; c < 64; c++) s = fmaf(Wq[r * 128 + 64 + c], w[c], s);
        v = s;
    }
    else if (j < 512) v = Wk[r * 128 + (j - 384)];
    else if (j < 640) v = Wv[r * 128 + (j - 512)];
    else              v = Ws[r * 128 + (j - 640)];
    g_Bcat[r * 768 + j] = v;

    if (r == 0) {
        float bv2;
        if (j < 128) bv2 = bq[j];
        else if (j < 256) {
            int d = j - 128; const float* w = We + d * 128;
            float s = 0.f;
            for (int c = 0; c < 64; c++) s = fmaf(bq[c], w[c], s);
            bv2 = s;
        } else if (j < 384) {
            int d = j - 256; const float* w = We + d * 128 + 64;
            float s = 0.f;
            for (int c = 0; c < 64; c++) s = fmaf(bq[64 + c], w[c], s);
            bv2 = s;
        }
        else if (j < 512) bv2 = bk[j - 384];
        else if (j < 640) bv2 = bv[j - 512];
        else              bv2 = bs[j - 640];
        g_bcat[j] = bv2;
    }
}

__global__ __launch_bounds__(256) void prep_bblk(const float* __restrict__ We)
{
    int n = blockIdx.x;      // 0..127
    int k = threadIdx.x;     // 0..255
    float v = 0.f;
    if (k < 128) { if (n < 64)  v = We[k * 128 + n]; }
    else         { if (n >= 64) v = We[(k - 128) * 128 + n]; }
    g_Bblk[k * 128 + n] = v;
}

// ---------------------------------------------------------------------------
// Edge binning (counting sort by dst)
// ---------------------------------------------------------------------------
__global__ __launch_bounds__(256) void hist_k(const int* __restrict__ ei, int E)
{
    int i = blockIdx.x * 256 + threadIdx.x;
    if (i < E) atomicAdd(&g_cnt[ei[E + i]], 1);
}

__global__ __launch_bounds__(512) void scan1_k(int N)
{
    __shared__ int sh[512];
    int tid = threadIdx.x;
    int i = blockIdx.x * 512 + tid;
    int v = (i < N) ? g_cnt[i] : 0;
    sh[tid] = v;
    __syncthreads();
#pragma unroll
    for (int o = 1; o < 512; o <<= 1) {
        int t = (tid >= o) ? sh[tid - o] : 0;
        __syncthreads();
        sh[tid] += t;
        __syncthreads();
    }
    if (i < N) g_off[i] = sh[tid] - v;        // exclusive within block
    if (tid == 511) g_bsum[blockIdx.x] = sh[511];
}

__global__ __launch_bounds__(256) void scan2_k(int nb)
{
    __shared__ int sh[256];
    int tid = threadIdx.x;
    int v = (tid < nb) ? g_bsum[tid] : 0;
    sh[tid] = v;
    __syncthreads();
#pragma unroll
    for (int o = 1; o < 256; o <<= 1) {
        int t = (tid >= o) ? sh[tid - o] : 0;
        __syncthreads();
        sh[tid] += t;
        __syncthreads();
    }
    if (tid < nb) g_bsum[tid] = sh[tid] - v;  // exclusive block offsets
}

__global__ __launch_bounds__(512) void scan3_k(int N)
{
    int i = blockIdx.x * 512 + threadIdx.x;
    if (i < N) {
        int o = g_off[i] + g_bsum[i >> 9];
        g_off[i] = o;
        g_cur[i] = o;
    }
}

__global__ __launch_bounds__(256) void scatter_k(const int* __restrict__ ei, int E)
{
    int e = blockIdx.x * 256 + threadIdx.x;
    if (e >= E) return;
    int dst = ei[E + e];
    int pos = atomicAdd(&g_cur[dst], 1);
    g_edges[pos] = make_int2(ei[e], e);
}

// ---------------------------------------------------------------------------
// Aggregation: one warp per destination node, no atomics, local normalize.
// ---------------------------------------------------------------------------
__device__ __forceinline__ float cos_acc(float x) {
    float k = rintf(x * 0.15915494309189535f);
    float r = (float)((double)x - (double)k * 6.283185307179586);
    return cosf(r);
}
__device__ __forceinline__ float wsum(float v) {
#pragma unroll
    for (int o = 16; o; o >>= 1) v += __shfl_xor_sync(0xffffffffu, v, o);
    return v;
}
__device__ __forceinline__ float dot4(float4 a, float4 b) {
    return a.x * b.x + a.y * b.y + a.z * b.z + a.w * b.w;
}

__global__ __launch_bounds__(256) void agg_k(
    const float* __restrict__ lu, const float* __restrict__ tt,
    const float* __restrict__ msg,
    const float* __restrict__ wt, const float* __restrict__ bt, int N)
{
    int n = (int)((blockIdx.x * 256 + threadIdx.x) >> 5);
    int lane = threadIdx.x & 31;
    if (n >= N) return;

    int off = g_off[n];
    int deg = g_cnt[n];

    const float4* QU4 = (const float4*)(g_QU + (size_t)n * 384);
    float4 q4 = QU4[lane];
    float4 u0 = QU4[32 + lane];
    float4 u1 = QU4[64 + lane];

    float4 w4 = make_float4(0.f, 0.f, 0.f, 0.f), b4 = w4;
    if (lane < 16) {
        w4 = ((const float4*)wt)[lane];
        b4 = ((const float4*)bt)[lane];
    }

    float4 av = make_float4(0.f, 0.f, 0.f, 0.f);
    float4 A0 = av, A1 = av;
    float den0 = 0.f, den1 = 0.f;

    for (int i = 0; i < deg; i++) {
        int2 se = g_edges[off + i];
        int src = se.x;
        int e = se.y;
        float relt = lu[src] - tt[e];

        float4 ea;
        if (lane < 16) {
            ea.x = cos_acc(fmaf(relt, w4.x, b4.x));
            ea.y = cos_acc(fmaf(relt, w4.y, b4.y));
            ea.z = cos_acc(fmaf(relt, w4.z, b4.z));
            ea.w = cos_acc(fmaf(relt, w4.w, b4.w));
        } else {
            ea = ((const float4*)(msg + (size_t)e * 64))[lane - 16];
        }

        const float4* KV4 = (const float4*)(g_KV + (size_t)src * 256);
        float4 k4 = KV4[lane];
        float4 v4 = KV4[32 + lane];

        float pqk = dot4(q4, k4);
        float s0 = dot4(ea, u0) + (lane < 16 ? pqk : 0.f);
        float s1 = dot4(ea, u1) + (lane < 16 ? 0.f : pqk);
        s0 = wsum(s0);
        s1 = wsum(s1);

        float ex0 = expf(s0 * 0.125f);
        float ex1 = expf(s1 * 0.125f);
        den0 += ex0;
        den1 += ex1;

        float evv = (lane < 16) ? ex0 : ex1;
        av.x = fmaf(evv, v4.x, av.x);
        av.y = fmaf(evv, v4.y, av.y);
        av.z = fmaf(evv, v4.z, av.z);
        av.w = fmaf(evv, v4.w, av.w);
        A0.x = fmaf(ex0, ea.x, A0.x);
        A0.y = fmaf(ex0, ea.y, A0.y);
        A0.z = fmaf(ex0, ea.z, A0.z);
        A0.w = fmaf(ex0, ea.w, A0.w);
        A1.x = fmaf(ex1, ea.x, A1.x);
        A1.y = fmaf(ex1, ea.y, A1.y);
        A1.z = fmaf(ex1, ea.z, A1.z);
        A1.w = fmaf(ex1, ea.w, A1.w);
    }

    float inv0 = 1.f / (den0 + 1e-16f);
    float inv1 = 1.f / (den1 + 1e-16f);
    float invv = (lane < 16) ? inv0 : inv1;

    av.x *= invv; av.y *= invv; av.z *= invv; av.w *= invv;
    A0.x *= inv0; A0.y *= inv0; A0.z *= inv0; A0.w *= inv0;
    A1.x *= inv1; A1.y *= inv1; A1.z *= inv1; A1.w *= inv1;

    float4* acc4 = (float4*)(g_acc + (size_t)n * 384);
    acc4[lane]      = av;
    acc4[32 + lane] = A0;
    acc4[64 + lane] = A1;
}

// out += acc_v   (skip already in out from projection GEMM; e-part added by epilogue GEMM)
__global__ __launch_bounds__(256) void add_v_k(float* __restrict__ out, int N)
{
    int idx = blockIdx.x * 256 + threadIdx.x;
    if (idx >= N * 32) return;
    int n = idx >> 5, c4 = idx & 31;
    float4 o = ((float4*)out)[idx];
    float4 a = ((const float4*)(g_acc + (size_t)n * 384))[c4];
    o.x += a.x; o.y += a.y; o.z += a.z; o.w += a.w;
    ((float4*)out)[idx] = o;
}

// ---------------------------------------------------------------------------
extern "C" void kernel_launch(void* const* d_in, const int* in_sizes, int n_in,
                              void* d_out, int out_size)
{
    const float* x    = (const float*)d_in[0];
    const float* lu   = (const float*)d_in[1];
    const int*   ei   = (const int*)  d_in[2];
    const float* tt   = (const float*)d_in[3];
    const float* msg  = (const float*)d_in[4];
    const float* wt   = (const float*)d_in[5];
    const float* bt   = (const float*)d_in[6];
    const float* Wq   = (const float*)d_in[7];
    const float* bq   = (const float*)d_in[8];
    const float* Wk   = (const float*)d_in[9];
    const float* bk   = (const float*)d_in[10];
    const float* Wv   = (const float*)d_in[11];
    const float* bv   = (const float*)d_in[12];
    const float* We   = (const float*)d_in[13];
    const float* Ws   = (const float*)d_in[14];
    const float* bs   = (const float*)d_in[15];
    float* out = (float*)d_out;

    int N = in_sizes[1];
    int E = in_sizes[3];

    float *pacc, *pBcat, *pbcat, *pBblk;
    int* pcnt;
    cudaGetSymbolAddress((void**)&pacc,  g_acc);
    cudaGetSymbolAddress((void**)&pBcat, g_Bcat);
    cudaGetSymbolAddress((void**)&pbcat, g_bcat);
    cudaGetSymbolAddress((void**)&pBblk, g_Bblk);
    cudaGetSymbolAddress((void**)&pcnt,  g_cnt);

    // Edge binning chain (independent of GEMM inputs)
    cudaMemsetAsync(pcnt, 0, (size_t)N * sizeof(int));
    hist_k<<<(E + 255) / 256, 256>>>(ei, E);
    int nb = (N + 511) / 512;
    scan1_k<<<nb, 512>>>(N);
    scan2_k<<<1, 256>>>(nb);
    scan3_k<<<nb, 512>>>(N);
    scatter_k<<<(E + 255) / 256, 256>>>(ei, E);

    // Weight prep
    prep_bcat<<<768, 128>>>(Wq, bq, Wk, bk, Wv, bv, Ws, bs, We);
    prep_bblk<<<128, 256>>>(We);

    int gm = (N + 127) / 128;

    // Projection: [q|u0|u1|k|v|skip] = x @ Bcat + bcat   (split write: QU/KV/out)
    sgemm_v2<<<dim3(gm, 6), 128>>>(x, 128, pBcat, 768, out, 128, N, 128, pbcat, 0, 1);

    // Aggregation: one warp per destination node
    agg_k<<<(N + 7) / 8, 256>>>(lu, tt, msg, wt, bt, N);

    // Epilogue: out += acc_e[N x 256] @ Bblk[256 x 128]   (out already holds skip)
    sgemm_v2<<<dim3(gm, 1), 128>>>(pacc + 128, 384, pBblk, 128, out, 128, N, 256, nullptr, 1, 0);

    // out += acc_v
    add_v_k<<<(N * 32 + 255) / 256, 256>>>(out, N);
}

// round 4
// speedup vs baseline: 2.0586x; 2.0586x over previous
#include <cuda_runtime.h>
#include <math.h>
#include <stdint.h>

#define MAX_N 100000
#define MAX_E 600000

__device__ float g_QU  [(size_t)MAX_N * 384];  // q(128)|u0(128)|u1(128)
__device__ float g_KV  [(size_t)MAX_N * 256];  // k(128)|v(128)
__device__ float g_acc [(size_t)MAX_N * 256];  // normalized e-accumulators per head
__device__ float g_BcatT[768 * 128];           // [n][k]
__device__ float g_bcat[768];
__device__ float g_BblkT[128 * 256];           // [n][k]
__device__ int  g_cnt[MAX_N];
__device__ int  g_off[MAX_N];
__device__ int  g_cur[MAX_N];
__device__ int  g_bsum[256];
__device__ int2 g_edges[MAX_E];

// ---------------------------------------------------------------------------
// tf32 tensor-core GEMM. C[M x (128*gridDim.y)] = A[M x K] @ B (+bias)(+=C)
// BM=128, BN=128, BK=16, 256 thr (8 warps, 4x2), warp tile 64x64, m16n8k8.
// B passed TRANSPOSED: BT[n][k]. mode==1: split projection write.
// ---------------------------------------------------------------------------
__device__ __forceinline__ void cpz(unsigned dst, const void* src, int sz) {
    asm volatile("cp.async.cg.shared.global [%0], [%1], 16, %2;"
                 :: "r"(dst), "l"(src), "r"(sz));
}
__device__ __forceinline__ uint32_t to_tf32(float x) {
    uint32_t u; asm("cvt.rna.tf32.f32 %0, %1;" : "=r"(u) : "f"(x)); return u;
}
__device__ __forceinline__ void mma8(float* c, const uint32_t* a, const uint32_t* b) {
    asm volatile("mma.sync.aligned.m16n8k8.row.col.f32.tf32.tf32.f32 "
        "{%0,%1,%2,%3}, {%4,%5,%6,%7}, {%8,%9}, {%0,%1,%2,%3};"
        : "+f"(c[0]), "+f"(c[1]), "+f"(c[2]), "+f"(c[3])
        : "r"(a[0]), "r"(a[1]), "r"(a[2]), "r"(a[3]), "r"(b[0]), "r"(b[1]));
}

__global__ __launch_bounds__(256) void mma_gemm(
    const float* __restrict__ A, int lda,
    const float* __restrict__ BT, int ldb,
    float* __restrict__ C,
    int M, int K,
    const float* __restrict__ bias, int accum, int mode)
{
    __shared__ float As[2][128][20];
    __shared__ float Bs[2][128][20];
    const int tid = threadIdx.x;
    const int lane = tid & 31;
    const int warp = tid >> 5;
    const int wm = warp & 3, wn = warp >> 2;
    const int grp = lane >> 2, qd = lane & 3;
    const int bm0 = blockIdx.x * 128;
    const int bn0 = blockIdx.y * 128;

    float c[2][8][4];
#pragma unroll
    for (int i = 0; i < 2; i++)
#pragma unroll
        for (int j = 0; j < 8; j++)
#pragma unroll
            for (int u = 0; u < 4; u++) c[i][j][u] = 0.f;

    const int ntiles = K >> 4;

    auto cpA = [&](int kt, int buf) {
#pragma unroll
        for (int it = 0; it < 2; it++) {
            int idx = tid + 256 * it;
            int row = idx >> 2, ch = (idx & 3) * 4;
            int gr = bm0 + row;
            int grc = gr < M ? gr : (M - 1);
            const float* src = A + (size_t)grc * lda + kt * 16 + ch;
            unsigned dst = (unsigned)__cvta_generic_to_shared(&As[buf][row][ch]);
            cpz(dst, src, gr < M ? 16 : 0);
        }
    };
    auto cpB = [&](int kt, int buf) {
#pragma unroll
        for (int it = 0; it < 2; it++) {
            int idx = tid + 256 * it;
            int row = idx >> 2, ch = (idx & 3) * 4;
            const float* src = BT + (size_t)(bn0 + row) * ldb + kt * 16 + ch;
            unsigned dst = (unsigned)__cvta_generic_to_shared(&Bs[buf][row][ch]);
            cpz(dst, src, 16);
        }
    };

    cpA(0, 0); cpB(0, 0);
    asm volatile("cp.async.commit_group;");
    asm volatile("cp.async.wait_group 0;");
    __syncthreads();

    for (int t = 0; t < ntiles; t++) {
        int cur = t & 1, nxt = cur ^ 1;
        bool more = (t + 1 < ntiles);
        if (more) {
            cpA(t + 1, nxt); cpB(t + 1, nxt);
            asm volatile("cp.async.commit_group;");
        }
#pragma unroll
        for (int k8 = 0; k8 < 2; k8++) {
            int k0 = k8 * 8;
            uint32_t af[2][4], bf[8][2];
#pragma unroll
            for (int mt = 0; mt < 2; mt++) {
                int mr = wm * 32 + mt * 16 + grp;
                af[mt][0] = to_tf32(As[cur][mr    ][k0 + qd]);
                af[mt][1] = to_tf32(As[cur][mr + 8][k0 + qd]);
                af[mt][2] = to_tf32(As[cur][mr    ][k0 + qd + 4]);
                af[mt][3] = to_tf32(As[cur][mr + 8][k0 + qd + 4]);
            }
#pragma unroll
            for (int nt = 0; nt < 8; nt++) {
                int nr = wn * 64 + nt * 8 + grp;
                bf[nt][0] = to_tf32(Bs[cur][nr][k0 + qd]);
                bf[nt][1] = to_tf32(Bs[cur][nr][k0 + qd + 4]);
            }
#pragma unroll
            for (int mt = 0; mt < 2; mt++)
#pragma unroll
                for (int nt = 0; nt < 8; nt++)
                    mma8(c[mt][nt], af[mt], bf[nt]);
        }
        if (more) asm volatile("cp.async.wait_group 0;");
        __syncthreads();
    }

#pragma unroll
    for (int mt = 0; mt < 2; mt++)
#pragma unroll
        for (int nt = 0; nt < 8; nt++)
#pragma unroll
            for (int half = 0; half < 2; half++) {
                int row = bm0 + wm * 32 + mt * 16 + grp + half * 8;
                if (row >= M) continue;
                int col = bn0 + wn * 64 + nt * 8 + qd * 2;
#pragma unroll
                for (int u = 0; u < 2; u++) {
                    float v = c[mt][nt][half * 2 + u];
                    int cc = col + u;
                    if (bias) v += bias[cc];
                    float* cp;
                    if (mode == 0)       cp = &C[(size_t)row * 128 + cc];
                    else if (cc < 384)   cp = &g_QU[(size_t)row * 384 + cc];
                    else if (cc < 640)   cp = &g_KV[(size_t)row * 256 + (cc - 384)];
                    else                 cp = &C[(size_t)row * 128 + (cc - 640)];
                    if (accum) v += *cp;
                    *cp = v;
                }
            }
}

// ---------------------------------------------------------------------------
// Prep kernels
// ---------------------------------------------------------------------------
__global__ __launch_bounds__(128) void prep_bcat(
    const float* __restrict__ Wq, const float* __restrict__ bq,
    const float* __restrict__ Wk, const float* __restrict__ bk,
    const float* __restrict__ Wv, const float* __restrict__ bv,
    const float* __restrict__ Ws, const float* __restrict__ bs,
    const float* __restrict__ We, int N)
{
    // also zero g_cnt (so hist can run without a memset launch)
    for (int i = blockIdx.x * 128 + threadIdx.x; i < N; i += 768 * 128)
        g_cnt[i] = 0;

    int j = blockIdx.x;      // output col 0..767
    int r = threadIdx.x;     // k row 0..127
    float v;
    if (j < 128) v = Wq[r * 128 + j];
    else if (j < 256) {
        int d = j - 128; const float* w = We + d * 128;
        float s = 0.f;
#pragma unroll
        for (int c = 0; c < 64; c++) s = fmaf(Wq[r * 128 + c], w[c], s);
        v = s;
    } else if (j < 384) {
        int d = j - 256; const float* w = We + d * 128 + 64;
        float s = 0.f;
#pragma unroll
        for (int c = 0; c < 64; c++) s = fmaf(Wq[r * 128 + 64 + c], w[c], s);
        v = s;
    }
    else if (j < 512) v = Wk[r * 128 + (j - 384)];
    else if (j < 640) v = Wv[r * 128 + (j - 512)];
    else              v = Ws[r * 128 + (j - 640)];
    g_BcatT[j * 128 + r] = v;

    if (r == 0) {
        float bv2;
        if (j < 128) bv2 = bq[j];
        else if (j < 256) {
            int d = j - 128; const float* w = We + d * 128;
            float s = 0.f;
            for (int c = 0; c < 64; c++) s = fmaf(bq[c], w[c], s);
            bv2 = s;
        } else if (j < 384) {
            int d = j - 256; const float* w = We + d * 128 + 64;
            float s = 0.f;
            for (int c = 0; c < 64; c++) s = fmaf(bq[64 + c], w[c], s);
            bv2 = s;
        }
        else if (j < 512) bv2 = bk[j - 384];
        else if (j < 640) bv2 = bv[j - 512];
        else              bv2 = bs[j - 640];
        g_bcat[j] = bv2;
    }
}

__global__ __launch_bounds__(256) void prep_bblk(const float* __restrict__ We)
{
    int n = blockIdx.x;      // 0..127
    int k = threadIdx.x;     // 0..255
    float v = 0.f;
    if (k < 128) { if (n < 64)  v = We[k * 128 + n]; }
    else         { if (n >= 64) v = We[(k - 128) * 128 + n]; }
    g_BblkT[n * 256 + k] = v;
}

// ---------------------------------------------------------------------------
// Edge binning (counting sort by dst)
// ---------------------------------------------------------------------------
__global__ __launch_bounds__(256) void hist_k(const int* __restrict__ ei, int E)
{
    int i = blockIdx.x * 256 + threadIdx.x;
    if (i < E) atomicAdd(&g_cnt[ei[E + i]], 1);
}

__global__ __launch_bounds__(512) void scan1_k(int N)
{
    __shared__ int sh[512];
    int tid = threadIdx.x;
    int i = blockIdx.x * 512 + tid;
    int v = (i < N) ? g_cnt[i] : 0;
    sh[tid] = v;
    __syncthreads();
#pragma unroll
    for (int o = 1; o < 512; o <<= 1) {
        int t = (tid >= o) ? sh[tid - o] : 0;
        __syncthreads();
        sh[tid] += t;
        __syncthreads();
    }
    if (i < N) g_off[i] = sh[tid] - v;
    if (tid == 511) g_bsum[blockIdx.x] = sh[511];
}

__global__ __launch_bounds__(256) void scan2_k(int nb)
{
    __shared__ int sh[256];
    int tid = threadIdx.x;
    int v = (tid < nb) ? g_bsum[tid] : 0;
    sh[tid] = v;
    __syncthreads();
#pragma unroll
    for (int o = 1; o < 256; o <<= 1) {
        int t = (tid >= o) ? sh[tid - o] : 0;
        __syncthreads();
        sh[tid] += t;
        __syncthreads();
    }
    if (tid < nb) g_bsum[tid] = sh[tid] - v;
}

__global__ __launch_bounds__(512) void scan3_k(int N)
{
    int i = blockIdx.x * 512 + threadIdx.x;
    if (i < N) {
        int o = g_off[i] + g_bsum[i >> 9];
        g_off[i] = o;
        g_cur[i] = o;
    }
}

__global__ __launch_bounds__(256) void scatter_k(const int* __restrict__ ei, int E)
{
    int e = blockIdx.x * 256 + threadIdx.x;
    if (e >= E) return;
    int dst = ei[E + e];
    int pos = atomicAdd(&g_cur[dst], 1);
    g_edges[pos] = make_int2(ei[e], e);
}

// ---------------------------------------------------------------------------
// Aggregation: one warp per destination node, pipelined, fp32-only math.
// ---------------------------------------------------------------------------
__device__ __forceinline__ float coss(float x) {
    // Cody-Waite: 2*pi = 6.28125 + 1.93530717958623e-3 (k*C1 exact, k<=~720)
    float k = rintf(x * 0.15915494309189535f);
    float r = fmaf(k, -6.28125f, x);
    r = fmaf(k, -1.93530717958623e-3f, r);
    return __cosf(r);
}
__device__ __forceinline__ float wsum(float v) {
#pragma unroll
    for (int o = 16; o; o >>= 1) v += __shfl_xor_sync(0xffffffffu, v, o);
    return v;
}
__device__ __forceinline__ float dot4(float4 a, float4 b) {
    return a.x * b.x + a.y * b.y + a.z * b.z + a.w * b.w;
}
__device__ __forceinline__ float4 fma4(float s, float4 a, float4 acc) {
    acc.x = fmaf(s, a.x, acc.x);
    acc.y = fmaf(s, a.y, acc.y);
    acc.z = fmaf(s, a.z, acc.z);
    acc.w = fmaf(s, a.w, acc.w);
    return acc;
}

__global__ __launch_bounds__(256) void agg_k(
    const float* __restrict__ lu, const float* __restrict__ tt,
    const float* __restrict__ msg,
    const float* __restrict__ wt, const float* __restrict__ bt,
    float* __restrict__ out, int N)
{
    int n = (int)((blockIdx.x * 256 + threadIdx.x) >> 5);
    int lane = threadIdx.x & 31;
    if (n >= N) return;

    int off = g_off[n];
    int deg = g_cnt[n];

    const float4* QU4 = (const float4*)(g_QU + (size_t)n * 384);
    float4 q4 = QU4[lane];
    float4 u0 = QU4[32 + lane];
    float4 u1 = QU4[64 + lane];

    float4 w4 = make_float4(0.f, 0.f, 0.f, 0.f), b4 = w4;
    if (lane < 16) {
        w4 = ((const float4*)wt)[lane];
        b4 = ((const float4*)bt)[lane];
    }

    float4 av = make_float4(0.f, 0.f, 0.f, 0.f);
    float4 A0 = av, A1 = av;
    float den0 = 0.f, den1 = 0.f;

    int2 se = make_int2(0, 0);
    float lus = 0.f, tts = 0.f;
    float4 kk = av, vv = av, mg = av;
    if (deg > 0) {
        se = g_edges[off];
        lus = lu[se.x]; tts = tt[se.y];
        const float4* KV4 = (const float4*)(g_KV + (size_t)se.x * 256);
        kk = KV4[lane]; vv = KV4[32 + lane];
        if (lane >= 16) mg = ((const float4*)(msg + (size_t)se.y * 64))[lane - 16];
    }

    for (int i = 0; i < deg; i++) {
        // stage next edge (loads overlap with the reduction below)
        int2 se2 = se; float lus2 = 0.f, tts2 = 0.f;
        float4 kk2 = av, vv2 = av, mg2 = av;
        bool more = (i + 1 < deg);
        if (more) {
            se2 = g_edges[off + i + 1];
            lus2 = lu[se2.x]; tts2 = tt[se2.y];
            const float4* KV4 = (const float4*)(g_KV + (size_t)se2.x * 256);
            kk2 = KV4[lane]; vv2 = KV4[32 + lane];
            if (lane >= 16) mg2 = ((const float4*)(msg + (size_t)se2.y * 64))[lane - 16];
        }

        float relt = lus - tts;
        float4 ea;
        if (lane < 16) {
            ea.x = coss(fmaf(relt, w4.x, b4.x));
            ea.y = coss(fmaf(relt, w4.y, b4.y));
            ea.z = coss(fmaf(relt, w4.z, b4.z));
            ea.w = coss(fmaf(relt, w4.w, b4.w));
        } else {
            ea = mg;
        }

        float pqk = dot4(q4, kk);
        float s0 = dot4(ea, u0) + (lane < 16 ? pqk : 0.f);
        float s1 = dot4(ea, u1) + (lane < 16 ? 0.f : pqk);
        s0 = wsum(s0);
        s1 = wsum(s1);

        float ex0 = __expf(s0 * 0.125f);
        float ex1 = __expf(s1 * 0.125f);
        den0 += ex0;
        den1 += ex1;

        float evv = (lane < 16) ? ex0 : ex1;
        av = fma4(evv, vv, av);
        A0 = fma4(ex0, ea, A0);
        A1 = fma4(ex1, ea, A1);

        se = se2; lus = lus2; tts = tts2; kk = kk2; vv = vv2; mg = mg2;
    }

    float inv0 = 1.f / (den0 + 1e-16f);
    float inv1 = 1.f / (den1 + 1e-16f);
    float invv = (lane < 16) ? inv0 : inv1;

    // out already holds skip; add normalized v-part directly (sole writer per row)
    float4* op = ((float4*)out) + (size_t)n * 32 + lane;
    float4 o = *op;
    o.x += av.x * invv; o.y += av.y * invv;
    o.z += av.z * invv; o.w += av.w * invv;
    *op = o;

    A0.x *= inv0; A0.y *= inv0; A0.z *= inv0; A0.w *= inv0;
    A1.x *= inv1; A1.y *= inv1; A1.z *= inv1; A1.w *= inv1;
    float4* acc4 = (float4*)(g_acc + (size_t)n * 256);
    acc4[lane]      = A0;
    acc4[32 + lane] = A1;
}

// ---------------------------------------------------------------------------
extern "C" void kernel_launch(void* const* d_in, const int* in_sizes, int n_in,
                              void* d_out, int out_size)
{
    const float* x    = (const float*)d_in[0];
    const float* lu   = (const float*)d_in[1];
    const int*   ei   = (const int*)  d_in[2];
    const float* tt   = (const float*)d_in[3];
    const float* msg  = (const float*)d_in[4];
    const float* wt   = (const float*)d_in[5];
    const float* bt   = (const float*)d_in[6];
    const float* Wq   = (const float*)d_in[7];
    const float* bq   = (const float*)d_in[8];
    const float* Wk   = (const float*)d_in[9];
    const float* bk   = (const float*)d_in[10];
    const float* Wv   = (const float*)d_in[11];
    const float* bv   = (const float*)d_in[12];
    const float* We   = (const float*)d_in[13];
    const float* Ws   = (const float*)d_in[14];
    const float* bs   = (const float*)d_in[15];
    float* out = (float*)d_out;

    int N = in_sizes[1];
    int E = in_sizes[3];

    float *pacc, *pBcatT, *pbcat, *pBblkT;
    cudaGetSymbolAddress((void**)&pacc,   g_acc);
    cudaGetSymbolAddress((void**)&pBcatT, g_BcatT);
    cudaGetSymbolAddress((void**)&pbcat,  g_bcat);
    cudaGetSymbolAddress((void**)&pBblkT, g_BblkT);

    int gm = (N + 127) / 128;
    int nb = (N + 511) / 512;

    // launch index:                                                    // 0
    prep_bcat<<<768, 128>>>(Wq, bq, Wk, bk, Wv, bv, Ws, bs, We, N);
    prep_bblk<<<128, 256>>>(We);                                        // 1
    hist_k<<<(E + 255) / 256, 256>>>(ei, E);                            // 2
    scan1_k<<<nb, 512>>>(N);                                            // 3
    scan2_k<<<1, 256>>>(nb);                                            // 4
    // Projection (tf32 tensor cores): [q|u0|u1|k|v|skip] = x @ Bcat + bcat
    mma_gemm<<<dim3(gm, 6), 256>>>(x, 128, pBcatT, 128, out,            // 5 (profiled)
                                   N, 128, pbcat, 0, 1);
    scan3_k<<<nb, 512>>>(N);                                            // 6
    scatter_k<<<(E + 255) / 256, 256>>>(ei, E);                         // 7
    // Aggregation (warp per dst node), adds v-part into out
    agg_k<<<(N + 7) / 8, 256>>>(lu, tt, msg, wt, bt, out, N);           // 8
    // Epilogue (tf32): out += accE[N x 256] @ Bblk[256 x 128]
    mma_gemm<<<dim3(gm, 1), 256>>>(pacc, 256, pBblkT, 256, out,         // 9
                                   N, 256, nullptr, 1, 0);
}